// round 10
// baseline (speedup 1.0000x reference)
#include <cuda_runtime.h>
#include <cuda_bf16.h>
#include <cstdint>

// Problem constants (B=2, S=2048, NX=1024, H=16, D=64)
#define BB 2
#define SS 2048
#define NXC 1024
#define HH 16
#define DD 64
#define MTOK (BB*SS)   // 4096

// Scratch (device globals — no allocation allowed)
__device__ float g_q[(size_t)BB*HH*SS*DD];   // [B,H,S,D]
__device__ float g_k[(size_t)BB*HH*SS*DD];   // [B,H,D,S]  (TRANSPOSED)
__device__ float g_v[(size_t)BB*HH*SS*DD];   // [B,H,S,D]
__device__ float g_a[(size_t)BB*SS*NXC];     // merged-head attn out

// ---------------------------------------------------------------------------
// helpers
// ---------------------------------------------------------------------------
static __device__ __forceinline__ uint32_t f2tf(float f) {
    uint32_t r;
    asm("cvt.rna.tf32.f32 %0, %1;" : "=r"(r) : "f"(f));
    return r;
}
static __device__ __forceinline__ void mma1688(float* c, const uint32_t* a,
                                               const uint32_t* b) {
    asm volatile(
        "mma.sync.aligned.m16n8k8.row.col.f32.tf32.tf32.f32 "
        "{%0,%1,%2,%3}, {%4,%5,%6,%7}, {%8,%9}, {%0,%1,%2,%3};"
        : "+f"(c[0]), "+f"(c[1]), "+f"(c[2]), "+f"(c[3])
        : "r"(a[0]), "r"(a[1]), "r"(a[2]), "r"(a[3]),
          "r"(b[0]), "r"(b[1]));
}
static __device__ __forceinline__ void cpa16(void* s, const void* g) {
    uint32_t sa = (uint32_t)__cvta_generic_to_shared(s);
    asm volatile("cp.async.cg.shared.global [%0], [%1], 16;"
                 :: "r"(sa), "l"(g));
}
#define CP_COMMIT()  asm volatile("cp.async.commit_group;")
#define CP_WAIT1()   asm volatile("cp.async.wait_group 1;")
#define CP_WAIT0()   asm volatile("cp.async.wait_group 0;")

// ---------------------------------------------------------------------------
// tf32 tensor-core GEMM, cp.async double-buffered.
// C[128,128] tile; 8 warps (4x2), warp tile 32x64; BLK_K=32.
// smem holds raw f32; f32->tf32 (RN) at fragment-load time.
// mode 0: C = acc + bias        mode 1: scatter q/v [B,H,S,D], k [B,H,D,S]
// ---------------------------------------------------------------------------
#define ASTR 36
#define BSTR 136
#define STAGE_A (128 * ASTR)
#define STAGE_B (32 * BSTR)
#define GEMM_SMEM ((2 * (STAGE_A + STAGE_B)) * 4)   // 71680 bytes

__global__ __launch_bounds__(256)
void tc_gemm(const float* __restrict__ A, const float* __restrict__ Bm,
             const float* __restrict__ bias, float* __restrict__ C,
             int K, int N, int mode)
{
    extern __shared__ float gsm[];
    float* AsB = gsm;                    // [2][128*ASTR]
    float* BsB = gsm + 2 * STAGE_A;      // [2][32*BSTR]

    const int tid = threadIdx.x;
    const int lane = tid & 31;
    const int warp = tid >> 5;
    const int warp_m = warp >> 1;
    const int warp_n = warp & 1;
    const int row0 = blockIdx.y * 128;
    const int col0 = blockIdx.x * 128;
    const float* Ap = A ? A : g_a;

    float acc[2][8][4];
#pragma unroll
    for (int mi = 0; mi < 2; mi++)
#pragma unroll
        for (int ni = 0; ni < 8; ni++)
#pragma unroll
            for (int e = 0; e < 4; e++) acc[mi][ni][e] = 0.f;

    const int lr = lane >> 2;
    const int lc = lane & 3;

    // async stage of one 32-deep K chunk into buffer `st`
    auto issue = [&](int st, int k0) {
        float* Ad = AsB + st * STAGE_A;
        float* Bd = BsB + st * STAGE_B;
#pragma unroll
        for (int t = 0; t < 4; t++) {
            const int fid = tid + t * 256;
            const int r = fid >> 3;              // 0..127
            const int c4 = (fid & 7) << 2;       // 0..28
            cpa16(Ad + r * ASTR + c4, Ap + (size_t)(row0 + r) * K + k0 + c4);
        }
#pragma unroll
        for (int t = 0; t < 4; t++) {
            const int fid = tid + t * 256;
            const int kk = fid >> 5;             // 0..31
            const int c4 = (fid & 31) << 2;      // 0..124
            cpa16(Bd + kk * BSTR + c4, Bm + (size_t)(k0 + kk) * N + col0 + c4);
        }
    };

    const int nk = K / 32;
    issue(0, 0);
    CP_COMMIT();

    for (int i = 0; i < nk; i++) {
        if (i + 1 < nk) {
            issue((i + 1) & 1, (i + 1) * 32);
            CP_COMMIT();
            CP_WAIT1();
        } else {
            CP_WAIT0();
        }
        __syncthreads();

        const float* As = AsB + (i & 1) * STAGE_A;
        const float* Bs = BsB + (i & 1) * STAGE_B;
#pragma unroll
        for (int ks = 0; ks < 4; ks++) {
            uint32_t af[2][4];
#pragma unroll
            for (int mi = 0; mi < 2; mi++) {
                const int r = warp_m * 32 + mi * 16 + lr;
                const int c = ks * 8 + lc;
                af[mi][0] = f2tf(As[r * ASTR + c]);
                af[mi][1] = f2tf(As[(r + 8) * ASTR + c]);
                af[mi][2] = f2tf(As[r * ASTR + c + 4]);
                af[mi][3] = f2tf(As[(r + 8) * ASTR + c + 4]);
            }
            uint32_t bf[8][2];
#pragma unroll
            for (int ni = 0; ni < 8; ni++) {
                const int kk = ks * 8 + lc;
                const int n = warp_n * 64 + ni * 8 + lr;
                bf[ni][0] = f2tf(Bs[kk * BSTR + n]);
                bf[ni][1] = f2tf(Bs[(kk + 4) * BSTR + n]);
            }
#pragma unroll
            for (int mi = 0; mi < 2; mi++)
#pragma unroll
                for (int ni = 0; ni < 8; ni++)
                    mma1688(acc[mi][ni], af[mi], bf[ni]);
        }
        __syncthreads();   // all warps done with this buffer before refill
    }

#pragma unroll
    for (int mi = 0; mi < 2; mi++) {
#pragma unroll
        for (int ni = 0; ni < 8; ni++) {
            const int r = row0 + warp_m * 32 + mi * 16 + lr;
            const int c = col0 + warp_n * 64 + ni * 8 + 2 * lc;
#pragma unroll
            for (int e = 0; e < 4; e++) {
                const int row = r + (e >> 1) * 8;
                const int col = c + (e & 1);
                const float val = acc[mi][ni][e] + bias[col];
                if (mode == 0) {
                    C[(size_t)row * NXC + col] = val;
                } else {
                    const int bidx = row >> 11;
                    const int s = row & 2047;
                    const int which = col >> 10;
                    const int hd = col & 1023;
                    const int h = hd >> 6;
                    const int d = hd & 63;
                    if (which == 0) {
                        g_q[(((size_t)(bidx * HH + h)) * SS + s) * DD + d] = val;
                    } else if (which == 1) {
                        g_k[(((size_t)(bidx * HH + h)) * DD + d) * SS + s] = val;
                    } else {
                        g_v[(((size_t)(bidx * HH + h)) * SS + s) * DD + d] = val;
                    }
                }
            }
        }
    }
}

// ---------------------------------------------------------------------------
// Tensor-core flash attention, cp.async double-buffered K/V.
// One block = one (b,h) x 128-query tile, 8 warps; warp owns 16 query rows.
//   Qs [128][68] tf32 (staged once)     Ps [128][68] tf32 (warp-private rows)
//   KVbuf[2]: Ks [64][72] raw f32 [d][key], Vs [64][72] raw f32 [c][d]
// ---------------------------------------------------------------------------
#define QSTR 68
#define KSTR 72
#define KVSTAGE (2 * 64 * KSTR)                       // floats per stage (K+V)
#define ATTN_SMEM ((2 * 128 * QSTR + 2 * KVSTAGE) * 4)  // 143360 bytes

__global__ __launch_bounds__(256)
void attn_mma_kernel()
{
    extern __shared__ float asm_[];
    uint32_t* Qs = (uint32_t*)asm_;               // 128*QSTR (tf32)
    uint32_t* Ps = Qs + 128 * QSTR;               // 128*QSTR (tf32)
    float* KV = asm_ + 2 * 128 * QSTR;            // [2][KVSTAGE] raw f32

    const int bh = blockIdx.x;
    const int qt = blockIdx.y;
    const int q0 = qt * 128;
    const int tid = threadIdx.x;
    const int lane = tid & 31;
    const int warp = tid >> 5;
    const int lr = lane >> 2;
    const int lc = lane & 3;
    const int wr = warp * 16;

    const float* Qg  = g_q + (size_t)bh * SS * DD;    // [s][d]
    const float* KgT = g_k + (size_t)bh * DD * SS;    // [d][s]
    const float* Vg  = g_v + (size_t)bh * SS * DD;    // [s][d]

    // Stage Q tile [128][64] as tf32 (once)
#pragma unroll
    for (int t = 0; t < 8; t++) {
        const int fid = tid + t * 256;
        const int r = fid >> 4;
        const int c4 = (fid & 15) << 2;
        float4 v = *(const float4*)(Qg + (size_t)(q0 + r) * DD + c4);
        *(uint4*)&Qs[r * QSTR + c4] =
            make_uint4(f2tf(v.x), f2tf(v.y), f2tf(v.z), f2tf(v.w));
    }

    auto issue_kv = [&](int st, int k0) {
        float* Ks = KV + st * KVSTAGE;
        float* Vs = Ks + 64 * KSTR;
#pragma unroll
        for (int t = 0; t < 4; t++) {
            const int fid = tid + t * 256;
            const int r = fid >> 4;            // 0..63
            const int c4 = (fid & 15) << 2;    // 0..60
            cpa16(Ks + r * KSTR + c4, KgT + (size_t)r * SS + k0 + c4);
            cpa16(Vs + r * KSTR + c4, Vg + (size_t)(k0 + r) * DD + c4);
        }
    };

    float oacc[8][4];
#pragma unroll
    for (int ni = 0; ni < 8; ni++)
#pragma unroll
        for (int e = 0; e < 4; e++) oacc[ni][e] = 0.f;
    float m0 = -1e30f, m1 = -1e30f, l0 = 0.f, l1 = 0.f;
    const float scale = 0.125f;

    const int nkt = 2 * qt + 2;
    issue_kv(0, 0);
    CP_COMMIT();

    for (int kt = 0; kt < nkt; kt++) {
        const int k0 = kt * 64;
        if (kt + 1 < nkt) {
            issue_kv((kt + 1) & 1, (kt + 1) * 64);
            CP_COMMIT();
            CP_WAIT1();
        } else {
            CP_WAIT0();
        }
        __syncthreads();   // KV stage visible to all; Qs ready on iter 0

        const float* Ks = KV + (kt & 1) * KVSTAGE;
        const float* Vs = Ks + 64 * KSTR;

        // S = Q K^T : warp tile 16 x 64, k = 64 (8 steps)
        float sacc[8][4];
#pragma unroll
        for (int ni = 0; ni < 8; ni++)
#pragma unroll
            for (int e = 0; e < 4; e++) sacc[ni][e] = 0.f;
#pragma unroll
        for (int ks = 0; ks < 8; ks++) {
            uint32_t af[4];
            const int c = ks * 8 + lc;
            af[0] = Qs[(wr + lr) * QSTR + c];
            af[1] = Qs[(wr + lr + 8) * QSTR + c];
            af[2] = Qs[(wr + lr) * QSTR + c + 4];
            af[3] = Qs[(wr + lr + 8) * QSTR + c + 4];
#pragma unroll
            for (int ni = 0; ni < 8; ni++) {
                uint32_t bf[2];
                const int n = ni * 8 + lr;
                bf[0] = f2tf(Ks[c * KSTR + n]);
                bf[1] = f2tf(Ks[(c + 4) * KSTR + n]);
                mma1688(sacc[ni], af, bf);
            }
        }

        // scale + causal mask (only tiles that intersect the diagonal)
        const bool need_mask = (k0 + 63 > q0);
        const int r0g = q0 + wr + lr;
        const int r1g = r0g + 8;
#pragma unroll
        for (int ni = 0; ni < 8; ni++) {
            const int c0g = k0 + ni * 8 + 2 * lc;
#pragma unroll
            for (int e = 0; e < 4; e++) sacc[ni][e] *= scale;
            if (need_mask) {
                if (c0g     > r0g) sacc[ni][0] = -1e30f;
                if (c0g + 1 > r0g) sacc[ni][1] = -1e30f;
                if (c0g     > r1g) sacc[ni][2] = -1e30f;
                if (c0g + 1 > r1g) sacc[ni][3] = -1e30f;
            }
        }

        // online softmax (rows lr / lr+8; quad reduction over lanes lc)
        float mx0 = -1e30f, mx1 = -1e30f;
#pragma unroll
        for (int ni = 0; ni < 8; ni++) {
            mx0 = fmaxf(mx0, fmaxf(sacc[ni][0], sacc[ni][1]));
            mx1 = fmaxf(mx1, fmaxf(sacc[ni][2], sacc[ni][3]));
        }
        mx0 = fmaxf(mx0, __shfl_xor_sync(0xffffffffu, mx0, 1));
        mx0 = fmaxf(mx0, __shfl_xor_sync(0xffffffffu, mx0, 2));
        mx1 = fmaxf(mx1, __shfl_xor_sync(0xffffffffu, mx1, 1));
        mx1 = fmaxf(mx1, __shfl_xor_sync(0xffffffffu, mx1, 2));

        const float mn0 = fmaxf(m0, mx0);
        const float mn1 = fmaxf(m1, mx1);
        const float a0 = __expf(m0 - mn0);
        const float a1 = __expf(m1 - mn1);
        m0 = mn0; m1 = mn1;

        float sum0 = 0.f, sum1 = 0.f;
#pragma unroll
        for (int ni = 0; ni < 8; ni++) {
            const float p0 = __expf(sacc[ni][0] - mn0);
            const float p1 = __expf(sacc[ni][1] - mn0);
            const float p2 = __expf(sacc[ni][2] - mn1);
            const float p3 = __expf(sacc[ni][3] - mn1);
            sum0 += p0 + p1;
            sum1 += p2 + p3;
            const int co = ni * 8 + 2 * lc;
            *(uint2*)&Ps[(wr + lr) * QSTR + co]     = make_uint2(f2tf(p0), f2tf(p1));
            *(uint2*)&Ps[(wr + lr + 8) * QSTR + co] = make_uint2(f2tf(p2), f2tf(p3));
        }
        sum0 += __shfl_xor_sync(0xffffffffu, sum0, 1);
        sum0 += __shfl_xor_sync(0xffffffffu, sum0, 2);
        sum1 += __shfl_xor_sync(0xffffffffu, sum1, 1);
        sum1 += __shfl_xor_sync(0xffffffffu, sum1, 2);
        l0 = l0 * a0 + sum0;
        l1 = l1 * a1 + sum1;

#pragma unroll
        for (int ni = 0; ni < 8; ni++) {
            oacc[ni][0] *= a0; oacc[ni][1] *= a0;
            oacc[ni][2] *= a1; oacc[ni][3] *= a1;
        }
        __syncwarp();   // P rows warp-private: order STS -> LDS within warp

        // O += P V
#pragma unroll
        for (int ks = 0; ks < 8; ks++) {
            uint32_t af[4];
            const int c = ks * 8 + lc;
            af[0] = Ps[(wr + lr) * QSTR + c];
            af[1] = Ps[(wr + lr + 8) * QSTR + c];
            af[2] = Ps[(wr + lr) * QSTR + c + 4];
            af[3] = Ps[(wr + lr + 8) * QSTR + c + 4];
#pragma unroll
            for (int ni = 0; ni < 8; ni++) {
                uint32_t bf[2];
                const int n = ni * 8 + lr;
                bf[0] = f2tf(Vs[c * KSTR + n]);
                bf[1] = f2tf(Vs[(c + 4) * KSTR + n]);
                mma1688(oacc[ni], af, bf);
            }
        }
        __syncthreads();   // buffer free before it is refilled next iteration
    }

    // Normalize + write to g_a[b][s][h*64+d]
    const int b = bh >> 4;
    const int h = bh & 15;
    const float inv0 = 1.f / l0;
    const float inv1 = 1.f / l1;
    const int r0g = q0 + wr + lr;
#pragma unroll
    for (int ni = 0; ni < 8; ni++) {
        const int col = h * DD + ni * 8 + 2 * lc;
        float* d0 = g_a + ((size_t)(b * SS + r0g)) * NXC + col;
        float* d1 = g_a + ((size_t)(b * SS + r0g + 8)) * NXC + col;
        *(float2*)d0 = make_float2(oacc[ni][0] * inv0, oacc[ni][1] * inv0);
        *(float2*)d1 = make_float2(oacc[ni][2] * inv1, oacc[ni][3] * inv1);
    }
}

// ---------------------------------------------------------------------------
extern "C" void kernel_launch(void* const* d_in, const int* in_sizes, int n_in,
                              void* d_out, int out_size)
{
    const float* x      = (const float*)d_in[0];
    const float* w_attn = (const float*)d_in[1];
    const float* b_attn = (const float*)d_in[2];
    const float* w_proj = (const float*)d_in[3];
    const float* b_proj = (const float*)d_in[4];
    float* out = (float*)d_out;

    cudaFuncSetAttribute(tc_gemm,
                         cudaFuncAttributeMaxDynamicSharedMemorySize, GEMM_SMEM);
    cudaFuncSetAttribute(attn_mma_kernel,
                         cudaFuncAttributeMaxDynamicSharedMemorySize, ATTN_SMEM);

    // 1) QKV GEMM (cp.async-pipelined tf32); K written transposed [B,H,D,S]
    tc_gemm<<<dim3(24, 32), 256, GEMM_SMEM>>>(x, w_attn, b_attn, nullptr,
                                              NXC, 3 * NXC, 1);

    // 2) Tensor-core causal flash attention, double-buffered K/V
    attn_mma_kernel<<<dim3(BB * HH, SS / 128), 256, ATTN_SMEM>>>();

    // 3) Projection (cp.async-pipelined tf32)
    tc_gemm<<<dim3(8, 32), 256, GEMM_SMEM>>>(nullptr, w_proj, b_proj, out,
                                             NXC, NXC, 0);
}

// round 11
// speedup vs baseline: 1.1609x; 1.1609x over previous
#include <cuda_runtime.h>
#include <cuda_bf16.h>
#include <cstdint>

// Problem constants (B=2, S=2048, NX=1024, H=16, D=64)
#define BB 2
#define SS 2048
#define NXC 1024
#define HH 16
#define DD 64
#define MTOK (BB*SS)   // 4096

// Scratch (device globals — no allocation allowed)
__device__ float g_q[(size_t)BB*HH*SS*DD];   // [B,H,S,D]
__device__ float g_k[(size_t)BB*HH*SS*DD];   // [B,H,D,S]  (TRANSPOSED)
__device__ float g_v[(size_t)BB*HH*SS*DD];   // [B,H,S,D]
__device__ float g_a[(size_t)BB*SS*NXC];     // merged-head attn out

// ---------------------------------------------------------------------------
// helpers
// ---------------------------------------------------------------------------
static __device__ __forceinline__ uint32_t f2tf(float f) {
    uint32_t r;
    asm("cvt.rna.tf32.f32 %0, %1;" : "=r"(r) : "f"(f));
    return r;
}
static __device__ __forceinline__ void mma1688(float* c, const uint32_t* a,
                                               const uint32_t* b) {
    asm volatile(
        "mma.sync.aligned.m16n8k8.row.col.f32.tf32.tf32.f32 "
        "{%0,%1,%2,%3}, {%4,%5,%6,%7}, {%8,%9}, {%0,%1,%2,%3};"
        : "+f"(c[0]), "+f"(c[1]), "+f"(c[2]), "+f"(c[3])
        : "r"(a[0]), "r"(a[1]), "r"(a[2]), "r"(a[3]),
          "r"(b[0]), "r"(b[1]));
}

// ---------------------------------------------------------------------------
// tf32 tensor-core GEMM via mma.sync (R8 formulation: tf32 staged at STS,
// single-buffered — measured equal to the cp.async variant, fewer cvts).
// mode 0: C[row*1024+col] = acc + bias[col]    (projection)
// mode 1: scatter q/v to [B,H,S,D], k to [B,H,D,S]   (QKV; N = 3072)
// ---------------------------------------------------------------------------
#define ASTR 36
#define BSTR 136

__global__ __launch_bounds__(256)
void tc_gemm(const float* __restrict__ A, const float* __restrict__ Bm,
             const float* __restrict__ bias, float* __restrict__ C,
             int K, int N, int mode)
{
    __shared__ uint32_t As[128 * ASTR];
    __shared__ uint32_t Bs[32 * BSTR];

    const int tid = threadIdx.x;
    const int lane = tid & 31;
    const int warp = tid >> 5;
    const int warp_m = warp >> 1;
    const int warp_n = warp & 1;
    const int row0 = blockIdx.y * 128;
    const int col0 = blockIdx.x * 128;
    const float* Ap = A ? A : g_a;

    float acc[2][8][4];
#pragma unroll
    for (int mi = 0; mi < 2; mi++)
#pragma unroll
        for (int ni = 0; ni < 8; ni++)
#pragma unroll
            for (int e = 0; e < 4; e++) acc[mi][ni][e] = 0.f;

    const int lr = lane >> 2;
    const int lc = lane & 3;

    for (int k0 = 0; k0 < K; k0 += 32) {
#pragma unroll
        for (int t = 0; t < 4; t++) {
            const int fid = tid + t * 256;
            const int r = fid >> 3;
            const int c4 = (fid & 7) << 2;
            float4 v = *(const float4*)(Ap + (size_t)(row0 + r) * K + k0 + c4);
            *(uint4*)&As[r * ASTR + c4] =
                make_uint4(f2tf(v.x), f2tf(v.y), f2tf(v.z), f2tf(v.w));
        }
#pragma unroll
        for (int t = 0; t < 4; t++) {
            const int fid = tid + t * 256;
            const int kk = fid >> 5;
            const int c4 = (fid & 31) << 2;
            float4 v = *(const float4*)(Bm + (size_t)(k0 + kk) * N + col0 + c4);
            *(uint4*)&Bs[kk * BSTR + c4] =
                make_uint4(f2tf(v.x), f2tf(v.y), f2tf(v.z), f2tf(v.w));
        }
        __syncthreads();

#pragma unroll
        for (int ks = 0; ks < 4; ks++) {
            uint32_t af[2][4];
#pragma unroll
            for (int mi = 0; mi < 2; mi++) {
                const int r = warp_m * 32 + mi * 16 + lr;
                const int c = ks * 8 + lc;
                af[mi][0] = As[r * ASTR + c];
                af[mi][1] = As[(r + 8) * ASTR + c];
                af[mi][2] = As[r * ASTR + c + 4];
                af[mi][3] = As[(r + 8) * ASTR + c + 4];
            }
            uint32_t bf[8][2];
#pragma unroll
            for (int ni = 0; ni < 8; ni++) {
                const int kk = ks * 8 + lc;
                const int n = warp_n * 64 + ni * 8 + lr;
                bf[ni][0] = Bs[kk * BSTR + n];
                bf[ni][1] = Bs[(kk + 4) * BSTR + n];
            }
#pragma unroll
            for (int mi = 0; mi < 2; mi++)
#pragma unroll
                for (int ni = 0; ni < 8; ni++)
                    mma1688(acc[mi][ni], af[mi], bf[ni]);
        }
        __syncthreads();
    }

#pragma unroll
    for (int mi = 0; mi < 2; mi++) {
#pragma unroll
        for (int ni = 0; ni < 8; ni++) {
            const int r = row0 + warp_m * 32 + mi * 16 + lr;
            const int c = col0 + warp_n * 64 + ni * 8 + 2 * lc;
#pragma unroll
            for (int e = 0; e < 4; e++) {
                const int row = r + (e >> 1) * 8;
                const int col = c + (e & 1);
                const float val = acc[mi][ni][e] + bias[col];
                if (mode == 0) {
                    C[(size_t)row * NXC + col] = val;
                } else {
                    const int bidx = row >> 11;
                    const int s = row & 2047;
                    const int which = col >> 10;
                    const int hd = col & 1023;
                    const int h = hd >> 6;
                    const int d = hd & 63;
                    if (which == 0) {
                        g_q[(((size_t)(bidx * HH + h)) * SS + s) * DD + d] = val;
                    } else if (which == 1) {
                        g_k[(((size_t)(bidx * HH + h)) * DD + d) * SS + s] = val;
                    } else {
                        g_v[(((size_t)(bidx * HH + h)) * SS + s) * DD + d] = val;
                    }
                }
            }
        }
    }
}

// ---------------------------------------------------------------------------
// Tensor-core flash attention (R8 numerics, new scheduling):
//  - qt = 15 - blockIdx.y: heavy causal tiles launch FIRST (load balance)
//  - 106.5 KB smem -> 2 CTAs/SM: cross-CTA overlap of MMA vs softmax phases
// One block = one (b,h) x 128-query tile, 8 warps; warp owns 16 query rows.
// ---------------------------------------------------------------------------
#define QSTR 68
#define KSTR 72
#define ATTN_SMEM ((2*128*QSTR + 2*64*KSTR) * 4)   // 106496 bytes

__global__ __launch_bounds__(256)
void attn_mma_kernel()
{
    extern __shared__ uint32_t smem[];
    uint32_t* Qs = smem;                      // 128*68 tf32
    uint32_t* Ps = Qs + 128 * QSTR;           // 128*68 tf32
    uint32_t* Ks = Ps + 128 * QSTR;           // 64*72 tf32 [d][key]
    uint32_t* Vs = Ks + 64 * KSTR;            // 64*72 tf32 [c][d]

    const int bh = blockIdx.x;                // b*16+h
    const int qt = (gridDim.y - 1) - blockIdx.y;   // heavy tiles first
    const int q0 = qt * 128;
    const int tid = threadIdx.x;
    const int lane = tid & 31;
    const int warp = tid >> 5;
    const int lr = lane >> 2;                 // 0..7
    const int lc = lane & 3;                  // 0..3
    const int wr = warp * 16;                 // warp base row

    const float* Qg  = g_q + (size_t)bh * SS * DD;    // [s][d]
    const float* KgT = g_k + (size_t)bh * DD * SS;    // [d][s]
    const float* Vg  = g_v + (size_t)bh * SS * DD;    // [s][d]

    // Stage Q tile [128][64] as tf32
#pragma unroll
    for (int t = 0; t < 8; t++) {
        const int fid = tid + t * 256;
        const int r = fid >> 4;                // 0..127
        const int c4 = (fid & 15) << 2;        // 0..60
        float4 v = *(const float4*)(Qg + (size_t)(q0 + r) * DD + c4);
        *(uint4*)&Qs[r * QSTR + c4] =
            make_uint4(f2tf(v.x), f2tf(v.y), f2tf(v.z), f2tf(v.w));
    }

    float oacc[8][4];
#pragma unroll
    for (int ni = 0; ni < 8; ni++)
#pragma unroll
        for (int e = 0; e < 4; e++) oacc[ni][e] = 0.f;
    float m0 = -1e30f, m1 = -1e30f, l0 = 0.f, l1 = 0.f;
    const float scale = 0.125f;               // 1/sqrt(64)

    const int nkt = 2 * qt + 2;
    for (int kt = 0; kt < nkt; kt++) {
        const int k0 = kt * 64;

        __syncthreads();   // prev O-mma done (Ks/Vs free); Qs ready on iter 0
        // Stage K^T [d][key] and V [c][d] as tf32
#pragma unroll
        for (int t = 0; t < 4; t++) {
            const int fid = tid + t * 256;
            const int r = fid >> 4;            // 0..63
            const int c4 = (fid & 15) << 2;    // 0..60
            float4 kv = *(const float4*)(KgT + (size_t)r * SS + k0 + c4);
            *(uint4*)&Ks[r * KSTR + c4] =
                make_uint4(f2tf(kv.x), f2tf(kv.y), f2tf(kv.z), f2tf(kv.w));
            float4 vv = *(const float4*)(Vg + (size_t)(k0 + r) * DD + c4);
            *(uint4*)&Vs[r * KSTR + c4] =
                make_uint4(f2tf(vv.x), f2tf(vv.y), f2tf(vv.z), f2tf(vv.w));
        }
        __syncthreads();

        // S = Q K^T : warp tile 16 x 64 (8 n-tiles), k = 64 (8 steps)
        float sacc[8][4];
#pragma unroll
        for (int ni = 0; ni < 8; ni++)
#pragma unroll
            for (int e = 0; e < 4; e++) sacc[ni][e] = 0.f;
#pragma unroll
        for (int ks = 0; ks < 8; ks++) {
            uint32_t af[4];
            const int c = ks * 8 + lc;
            af[0] = Qs[(wr + lr) * QSTR + c];
            af[1] = Qs[(wr + lr + 8) * QSTR + c];
            af[2] = Qs[(wr + lr) * QSTR + c + 4];
            af[3] = Qs[(wr + lr + 8) * QSTR + c + 4];
#pragma unroll
            for (int ni = 0; ni < 8; ni++) {
                uint32_t bf[2];
                const int n = ni * 8 + lr;
                bf[0] = Ks[c * KSTR + n];
                bf[1] = Ks[(c + 4) * KSTR + n];
                mma1688(sacc[ni], af, bf);
            }
        }

        // scale + causal mask (only the tiles that intersect the diagonal)
        const bool need_mask = (k0 + 63 > q0);
        const int r0g = q0 + wr + lr;
        const int r1g = r0g + 8;
#pragma unroll
        for (int ni = 0; ni < 8; ni++) {
            const int c0g = k0 + ni * 8 + 2 * lc;
#pragma unroll
            for (int e = 0; e < 4; e++) sacc[ni][e] *= scale;
            if (need_mask) {
                if (c0g     > r0g) sacc[ni][0] = -1e30f;
                if (c0g + 1 > r0g) sacc[ni][1] = -1e30f;
                if (c0g     > r1g) sacc[ni][2] = -1e30f;
                if (c0g + 1 > r1g) sacc[ni][3] = -1e30f;
            }
        }

        // online softmax (rows lr / lr+8; quad reduction over lanes lc)
        float mx0 = -1e30f, mx1 = -1e30f;
#pragma unroll
        for (int ni = 0; ni < 8; ni++) {
            mx0 = fmaxf(mx0, fmaxf(sacc[ni][0], sacc[ni][1]));
            mx1 = fmaxf(mx1, fmaxf(sacc[ni][2], sacc[ni][3]));
        }
        mx0 = fmaxf(mx0, __shfl_xor_sync(0xffffffffu, mx0, 1));
        mx0 = fmaxf(mx0, __shfl_xor_sync(0xffffffffu, mx0, 2));
        mx1 = fmaxf(mx1, __shfl_xor_sync(0xffffffffu, mx1, 1));
        mx1 = fmaxf(mx1, __shfl_xor_sync(0xffffffffu, mx1, 2));

        const float mn0 = fmaxf(m0, mx0);
        const float mn1 = fmaxf(m1, mx1);
        const float a0 = __expf(m0 - mn0);
        const float a1 = __expf(m1 - mn1);
        m0 = mn0; m1 = mn1;

        float sum0 = 0.f, sum1 = 0.f;
#pragma unroll
        for (int ni = 0; ni < 8; ni++) {
            const float p0 = __expf(sacc[ni][0] - mn0);
            const float p1 = __expf(sacc[ni][1] - mn0);
            const float p2 = __expf(sacc[ni][2] - mn1);
            const float p3 = __expf(sacc[ni][3] - mn1);
            sum0 += p0 + p1;
            sum1 += p2 + p3;
            const int co = ni * 8 + 2 * lc;
            *(uint2*)&Ps[(wr + lr) * QSTR + co]     = make_uint2(f2tf(p0), f2tf(p1));
            *(uint2*)&Ps[(wr + lr + 8) * QSTR + co] = make_uint2(f2tf(p2), f2tf(p3));
        }
        sum0 += __shfl_xor_sync(0xffffffffu, sum0, 1);
        sum0 += __shfl_xor_sync(0xffffffffu, sum0, 2);
        sum1 += __shfl_xor_sync(0xffffffffu, sum1, 1);
        sum1 += __shfl_xor_sync(0xffffffffu, sum1, 2);
        l0 = l0 * a0 + sum0;
        l1 = l1 * a1 + sum1;

#pragma unroll
        for (int ni = 0; ni < 8; ni++) {
            oacc[ni][0] *= a0; oacc[ni][1] *= a0;
            oacc[ni][2] *= a1; oacc[ni][3] *= a1;
        }
        __syncwarp();   // P rows are warp-private; order STS -> LDS in-warp

        // O += P V : k = 64 keys (8 steps), 8 d-tiles
#pragma unroll
        for (int ks = 0; ks < 8; ks++) {
            uint32_t af[4];
            const int c = ks * 8 + lc;
            af[0] = Ps[(wr + lr) * QSTR + c];
            af[1] = Ps[(wr + lr + 8) * QSTR + c];
            af[2] = Ps[(wr + lr) * QSTR + c + 4];
            af[3] = Ps[(wr + lr + 8) * QSTR + c + 4];
#pragma unroll
            for (int ni = 0; ni < 8; ni++) {
                uint32_t bf[2];
                const int n = ni * 8 + lr;
                bf[0] = Vs[c * KSTR + n];
                bf[1] = Vs[(c + 4) * KSTR + n];
                mma1688(oacc[ni], af, bf);
            }
        }
    }

    // Normalize + write to g_a[b][s][h*64+d]
    const int b = bh >> 4;
    const int h = bh & 15;
    const float inv0 = 1.f / l0;
    const float inv1 = 1.f / l1;
    const int r0g = q0 + wr + lr;
#pragma unroll
    for (int ni = 0; ni < 8; ni++) {
        const int col = h * DD + ni * 8 + 2 * lc;
        float* d0 = g_a + ((size_t)(b * SS + r0g)) * NXC + col;
        float* d1 = g_a + ((size_t)(b * SS + r0g + 8)) * NXC + col;
        *(float2*)d0 = make_float2(oacc[ni][0] * inv0, oacc[ni][1] * inv0);
        *(float2*)d1 = make_float2(oacc[ni][2] * inv1, oacc[ni][3] * inv1);
    }
}

// ---------------------------------------------------------------------------
extern "C" void kernel_launch(void* const* d_in, const int* in_sizes, int n_in,
                              void* d_out, int out_size)
{
    const float* x      = (const float*)d_in[0];
    const float* w_attn = (const float*)d_in[1];
    const float* b_attn = (const float*)d_in[2];
    const float* w_proj = (const float*)d_in[3];
    const float* b_proj = (const float*)d_in[4];
    float* out = (float*)d_out;

    cudaFuncSetAttribute(attn_mma_kernel,
                         cudaFuncAttributeMaxDynamicSharedMemorySize, ATTN_SMEM);

    // 1) QKV GEMM (mma.sync tf32); K written transposed [B,H,D,S]
    tc_gemm<<<dim3(24, 32), 256>>>(x, w_attn, b_attn, nullptr, NXC, 3 * NXC, 1);

    // 2) Tensor-core causal flash attention, heavy-tile-first scheduling
    attn_mma_kernel<<<dim3(BB * HH, SS / 128), 256, ATTN_SMEM>>>();

    // 3) Projection (mma.sync tf32)
    tc_gemm<<<dim3(8, 32), 256>>>(nullptr, w_proj, b_proj, out, NXC, NXC, 0);
}

// round 13
// speedup vs baseline: 1.1657x; 1.0041x over previous
#include <cuda_runtime.h>
#include <cuda_bf16.h>
#include <cstdint>

// Problem constants (B=2, S=2048, NX=1024, H=16, D=64)
#define BB 2
#define SS 2048
#define NXC 1024
#define HH 16
#define DD 64
#define MTOK (BB*SS)   // 4096

// Scratch (device globals — no allocation allowed). All values stored here
// are tf32-rounded f32 (low mantissa bits zero), so GEMMs load them raw.
// NOTE: these symbols are referenced ONLY inside device code — passing them
// as kernel arguments from host was the R12 bug (host shadow address).
__device__ float g_q[(size_t)BB*HH*SS*DD];    // [B,H,S,D]   tf32-rounded
__device__ float g_k[(size_t)BB*HH*SS*DD];    // [B,H,D,S]   tf32-rounded (transposed)
__device__ float g_v[(size_t)BB*HH*SS*DD];    // [B,H,S,D]   tf32-rounded
__device__ float g_a[(size_t)BB*SS*NXC];      // attn out    tf32-rounded
__device__ float g_xtf[(size_t)MTOK*NXC];     // x           tf32-rounded
__device__ float g_w1[(size_t)NXC*3*NXC];     // w_attn      tf32-rounded
__device__ float g_w2[(size_t)NXC*NXC];       // w_proj      tf32-rounded

// ---------------------------------------------------------------------------
// helpers
// ---------------------------------------------------------------------------
static __device__ __forceinline__ uint32_t f2tf(float f) {
    uint32_t r;
    asm("cvt.rna.tf32.f32 %0, %1;" : "=r"(r) : "f"(f));
    return r;
}
static __device__ __forceinline__ void mma1688(float* c, const uint32_t* a,
                                               const uint32_t* b) {
    asm volatile(
        "mma.sync.aligned.m16n8k8.row.col.f32.tf32.tf32.f32 "
        "{%0,%1,%2,%3}, {%4,%5,%6,%7}, {%8,%9}, {%0,%1,%2,%3};"
        : "+f"(c[0]), "+f"(c[1]), "+f"(c[2]), "+f"(c[3])
        : "r"(a[0]), "r"(a[1]), "r"(a[2]), "r"(a[3]),
          "r"(b[0]), "r"(b[1]));
}
static __device__ __forceinline__ void cpa16(void* s, const void* g) {
    uint32_t sa = (uint32_t)__cvta_generic_to_shared(s);
    asm volatile("cp.async.cg.shared.global [%0], [%1], 16;"
                 :: "r"(sa), "l"(g));
}
#define CP_COMMIT()  asm volatile("cp.async.commit_group;")
#define CP_WAIT1()   asm volatile("cp.async.wait_group 1;")
#define CP_WAIT0()   asm volatile("cp.async.wait_group 0;")

// ---------------------------------------------------------------------------
// Elementwise f32 -> tf32-rounded f32 copy. dst: 0=g_xtf 1=g_w1 2=g_w2.
// ---------------------------------------------------------------------------
__global__ void cvt_tf32_kernel(const float* __restrict__ in, int dst)
{
    float* out = (dst == 0) ? g_xtf : (dst == 1) ? g_w1 : g_w2;
    const int i = (blockIdx.x * 256 + threadIdx.x) * 4;
    float4 v = *(const float4*)(in + i);
    *(uint4*)(out + i) =
        make_uint4(f2tf(v.x), f2tf(v.y), f2tf(v.z), f2tf(v.w));
}

// ---------------------------------------------------------------------------
// tf32 tensor-core GEMM: cp.async double-buffered, zero cvts in mainloop
// (operands pre-rounded in gmem). C tile 128x128; 8 warps, warp tile 32x64.
// Pointers resolved INSIDE the kernel from mode:
//   mode 1 (QKV):  A = g_xtf, B = g_w1, epilogue scatters rounded q/k/v
//   mode 0 (proj): A = g_a,   B = g_w2, epilogue C = acc + bias (f32)
// ---------------------------------------------------------------------------
#define ASTR 36
#define BSTR 136
#define STAGE_A (128 * ASTR)
#define STAGE_B (32 * BSTR)
#define GEMM_SMEM ((2 * (STAGE_A + STAGE_B)) * 4)   // 71680 bytes

__global__ __launch_bounds__(256)
void tc_gemm(const float* __restrict__ bias, float* __restrict__ C,
             int K, int N, int mode)
{
    extern __shared__ float gsm[];
    float* AsB = gsm;                    // [2][128*ASTR]
    float* BsB = gsm + 2 * STAGE_A;      // [2][32*BSTR]

    const int tid = threadIdx.x;
    const int lane = tid & 31;
    const int warp = tid >> 5;
    const int warp_m = warp >> 1;
    const int warp_n = warp & 1;
    const int row0 = blockIdx.y * 128;
    const int col0 = blockIdx.x * 128;
    const float* Ap = mode ? g_xtf : g_a;
    const float* Bm = mode ? g_w1 : g_w2;

    float acc[2][8][4];
#pragma unroll
    for (int mi = 0; mi < 2; mi++)
#pragma unroll
        for (int ni = 0; ni < 8; ni++)
#pragma unroll
            for (int e = 0; e < 4; e++) acc[mi][ni][e] = 0.f;

    const int lr = lane >> 2;
    const int lc = lane & 3;

    auto issue = [&](int st, int k0) {
        float* Ad = AsB + st * STAGE_A;
        float* Bd = BsB + st * STAGE_B;
#pragma unroll
        for (int t = 0; t < 4; t++) {
            const int fid = tid + t * 256;
            const int r = fid >> 3;              // 0..127
            const int c4 = (fid & 7) << 2;       // 0..28
            cpa16(Ad + r * ASTR + c4, Ap + (size_t)(row0 + r) * K + k0 + c4);
        }
#pragma unroll
        for (int t = 0; t < 4; t++) {
            const int fid = tid + t * 256;
            const int kk = fid >> 5;             // 0..31
            const int c4 = (fid & 31) << 2;      // 0..124
            cpa16(Bd + kk * BSTR + c4, Bm + (size_t)(k0 + kk) * N + col0 + c4);
        }
    };

    const int nk = K / 32;
    issue(0, 0);
    CP_COMMIT();

    for (int i = 0; i < nk; i++) {
        if (i + 1 < nk) {
            issue((i + 1) & 1, (i + 1) * 32);
            CP_COMMIT();
            CP_WAIT1();
        } else {
            CP_WAIT0();
        }
        __syncthreads();

        const uint32_t* As = (const uint32_t*)(AsB + (i & 1) * STAGE_A);
        const uint32_t* Bs = (const uint32_t*)(BsB + (i & 1) * STAGE_B);
#pragma unroll
        for (int ks = 0; ks < 4; ks++) {
            uint32_t af[2][4];
#pragma unroll
            for (int mi = 0; mi < 2; mi++) {
                const int r = warp_m * 32 + mi * 16 + lr;
                const int c = ks * 8 + lc;
                af[mi][0] = As[r * ASTR + c];
                af[mi][1] = As[(r + 8) * ASTR + c];
                af[mi][2] = As[r * ASTR + c + 4];
                af[mi][3] = As[(r + 8) * ASTR + c + 4];
            }
            uint32_t bf[8][2];
#pragma unroll
            for (int ni = 0; ni < 8; ni++) {
                const int kk = ks * 8 + lc;
                const int n = warp_n * 64 + ni * 8 + lr;
                bf[ni][0] = Bs[kk * BSTR + n];
                bf[ni][1] = Bs[(kk + 4) * BSTR + n];
            }
#pragma unroll
            for (int mi = 0; mi < 2; mi++)
#pragma unroll
                for (int ni = 0; ni < 8; ni++)
                    mma1688(acc[mi][ni], af[mi], bf[ni]);
        }
        __syncthreads();
    }

#pragma unroll
    for (int mi = 0; mi < 2; mi++) {
#pragma unroll
        for (int ni = 0; ni < 8; ni++) {
            const int r = row0 + warp_m * 32 + mi * 16 + lr;
            const int c = col0 + warp_n * 64 + ni * 8 + 2 * lc;
#pragma unroll
            for (int e = 0; e < 4; e++) {
                const int row = r + (e >> 1) * 8;
                const int col = c + (e & 1);
                const float val = acc[mi][ni][e] + bias[col];
                if (mode == 0) {
                    C[(size_t)row * NXC + col] = val;
                } else {
                    // store tf32-rounded so attention can load raw
                    const float rv = __uint_as_float(f2tf(val));
                    const int bidx = row >> 11;
                    const int s = row & 2047;
                    const int which = col >> 10;
                    const int hd = col & 1023;
                    const int h = hd >> 6;
                    const int d = hd & 63;
                    if (which == 0) {
                        g_q[(((size_t)(bidx * HH + h)) * SS + s) * DD + d] = rv;
                    } else if (which == 1) {
                        g_k[(((size_t)(bidx * HH + h)) * DD + d) * SS + s] = rv;
                    } else {
                        g_v[(((size_t)(bidx * HH + h)) * SS + s) * DD + d] = rv;
                    }
                }
            }
        }
    }
}

// ---------------------------------------------------------------------------
// Tensor-core flash attention (R11 structure: heavy-first, 2 CTAs/SM),
// staging is raw uint4 copies (inputs pre-rounded to tf32).
// One block = one (b,h) x 128-query tile, 8 warps; warp owns 16 query rows.
// ---------------------------------------------------------------------------
#define QSTR 68
#define KSTR 72
#define ATTN_SMEM ((2*128*QSTR + 2*64*KSTR) * 4)   // 106496 bytes

__global__ __launch_bounds__(256)
void attn_mma_kernel()
{
    extern __shared__ uint32_t smem[];
    uint32_t* Qs = smem;                      // 128*68 tf32
    uint32_t* Ps = Qs + 128 * QSTR;           // 128*68 tf32
    uint32_t* Ks = Ps + 128 * QSTR;           // 64*72 tf32 [d][key]
    uint32_t* Vs = Ks + 64 * KSTR;            // 64*72 tf32 [c][d]

    const int bh = blockIdx.x;
    const int qt = (gridDim.y - 1) - blockIdx.y;   // heavy tiles first
    const int q0 = qt * 128;
    const int tid = threadIdx.x;
    const int lane = tid & 31;
    const int warp = tid >> 5;
    const int lr = lane >> 2;
    const int lc = lane & 3;
    const int wr = warp * 16;

    const float* Qg  = g_q + (size_t)bh * SS * DD;    // [s][d]
    const float* KgT = g_k + (size_t)bh * DD * SS;    // [d][s]
    const float* Vg  = g_v + (size_t)bh * SS * DD;    // [s][d]

    // Stage Q tile [128][64] — raw copy (already tf32-rounded)
#pragma unroll
    for (int t = 0; t < 8; t++) {
        const int fid = tid + t * 256;
        const int r = fid >> 4;
        const int c4 = (fid & 15) << 2;
        *(uint4*)&Qs[r * QSTR + c4] =
            *(const uint4*)(Qg + (size_t)(q0 + r) * DD + c4);
    }

    float oacc[8][4];
#pragma unroll
    for (int ni = 0; ni < 8; ni++)
#pragma unroll
        for (int e = 0; e < 4; e++) oacc[ni][e] = 0.f;
    float m0 = -1e30f, m1 = -1e30f, l0 = 0.f, l1 = 0.f;
    const float scale = 0.125f;

    const int nkt = 2 * qt + 2;
    for (int kt = 0; kt < nkt; kt++) {
        const int k0 = kt * 64;

        __syncthreads();
#pragma unroll
        for (int t = 0; t < 4; t++) {
            const int fid = tid + t * 256;
            const int r = fid >> 4;
            const int c4 = (fid & 15) << 2;
            *(uint4*)&Ks[r * KSTR + c4] =
                *(const uint4*)(KgT + (size_t)r * SS + k0 + c4);
            *(uint4*)&Vs[r * KSTR + c4] =
                *(const uint4*)(Vg + (size_t)(k0 + r) * DD + c4);
        }
        __syncthreads();

        // S = Q K^T
        float sacc[8][4];
#pragma unroll
        for (int ni = 0; ni < 8; ni++)
#pragma unroll
            for (int e = 0; e < 4; e++) sacc[ni][e] = 0.f;
#pragma unroll
        for (int ks = 0; ks < 8; ks++) {
            uint32_t af[4];
            const int c = ks * 8 + lc;
            af[0] = Qs[(wr + lr) * QSTR + c];
            af[1] = Qs[(wr + lr + 8) * QSTR + c];
            af[2] = Qs[(wr + lr) * QSTR + c + 4];
            af[3] = Qs[(wr + lr + 8) * QSTR + c + 4];
#pragma unroll
            for (int ni = 0; ni < 8; ni++) {
                uint32_t bf[2];
                const int n = ni * 8 + lr;
                bf[0] = Ks[c * KSTR + n];
                bf[1] = Ks[(c + 4) * KSTR + n];
                mma1688(sacc[ni], af, bf);
            }
        }

        const bool need_mask = (k0 + 63 > q0);
        const int r0g = q0 + wr + lr;
        const int r1g = r0g + 8;
#pragma unroll
        for (int ni = 0; ni < 8; ni++) {
            const int c0g = k0 + ni * 8 + 2 * lc;
#pragma unroll
            for (int e = 0; e < 4; e++) sacc[ni][e] *= scale;
            if (need_mask) {
                if (c0g     > r0g) sacc[ni][0] = -1e30f;
                if (c0g + 1 > r0g) sacc[ni][1] = -1e30f;
                if (c0g     > r1g) sacc[ni][2] = -1e30f;
                if (c0g + 1 > r1g) sacc[ni][3] = -1e30f;
            }
        }

        // online softmax
        float mx0 = -1e30f, mx1 = -1e30f;
#pragma unroll
        for (int ni = 0; ni < 8; ni++) {
            mx0 = fmaxf(mx0, fmaxf(sacc[ni][0], sacc[ni][1]));
            mx1 = fmaxf(mx1, fmaxf(sacc[ni][2], sacc[ni][3]));
        }
        mx0 = fmaxf(mx0, __shfl_xor_sync(0xffffffffu, mx0, 1));
        mx0 = fmaxf(mx0, __shfl_xor_sync(0xffffffffu, mx0, 2));
        mx1 = fmaxf(mx1, __shfl_xor_sync(0xffffffffu, mx1, 1));
        mx1 = fmaxf(mx1, __shfl_xor_sync(0xffffffffu, mx1, 2));

        const float mn0 = fmaxf(m0, mx0);
        const float mn1 = fmaxf(m1, mx1);
        const float a0 = __expf(m0 - mn0);
        const float a1 = __expf(m1 - mn1);
        m0 = mn0; m1 = mn1;

        float sum0 = 0.f, sum1 = 0.f;
#pragma unroll
        for (int ni = 0; ni < 8; ni++) {
            const float p0 = __expf(sacc[ni][0] - mn0);
            const float p1 = __expf(sacc[ni][1] - mn0);
            const float p2 = __expf(sacc[ni][2] - mn1);
            const float p3 = __expf(sacc[ni][3] - mn1);
            sum0 += p0 + p1;
            sum1 += p2 + p3;
            const int co = ni * 8 + 2 * lc;
            *(uint2*)&Ps[(wr + lr) * QSTR + co]     = make_uint2(f2tf(p0), f2tf(p1));
            *(uint2*)&Ps[(wr + lr + 8) * QSTR + co] = make_uint2(f2tf(p2), f2tf(p3));
        }
        sum0 += __shfl_xor_sync(0xffffffffu, sum0, 1);
        sum0 += __shfl_xor_sync(0xffffffffu, sum0, 2);
        sum1 += __shfl_xor_sync(0xffffffffu, sum1, 1);
        sum1 += __shfl_xor_sync(0xffffffffu, sum1, 2);
        l0 = l0 * a0 + sum0;
        l1 = l1 * a1 + sum1;

#pragma unroll
        for (int ni = 0; ni < 8; ni++) {
            oacc[ni][0] *= a0; oacc[ni][1] *= a0;
            oacc[ni][2] *= a1; oacc[ni][3] *= a1;
        }
        __syncwarp();

        // O += P V
#pragma unroll
        for (int ks = 0; ks < 8; ks++) {
            uint32_t af[4];
            const int c = ks * 8 + lc;
            af[0] = Ps[(wr + lr) * QSTR + c];
            af[1] = Ps[(wr + lr + 8) * QSTR + c];
            af[2] = Ps[(wr + lr) * QSTR + c + 4];
            af[3] = Ps[(wr + lr + 8) * QSTR + c + 4];
#pragma unroll
            for (int ni = 0; ni < 8; ni++) {
                uint32_t bf[2];
                const int n = ni * 8 + lr;
                bf[0] = Vs[c * KSTR + n];
                bf[1] = Vs[(c + 4) * KSTR + n];
                mma1688(oacc[ni], af, bf);
            }
        }
    }

    // Normalize + write g_a tf32-rounded (projection loads raw)
    const int b = bh >> 4;
    const int h = bh & 15;
    const float inv0 = 1.f / l0;
    const float inv1 = 1.f / l1;
    const int r0g = q0 + wr + lr;
#pragma unroll
    for (int ni = 0; ni < 8; ni++) {
        const int col = h * DD + ni * 8 + 2 * lc;
        float* d0 = g_a + ((size_t)(b * SS + r0g)) * NXC + col;
        float* d1 = g_a + ((size_t)(b * SS + r0g + 8)) * NXC + col;
        *(uint2*)d0 = make_uint2(f2tf(oacc[ni][0] * inv0),
                                 f2tf(oacc[ni][1] * inv0));
        *(uint2*)d1 = make_uint2(f2tf(oacc[ni][2] * inv1),
                                 f2tf(oacc[ni][3] * inv1));
    }
}

// ---------------------------------------------------------------------------
extern "C" void kernel_launch(void* const* d_in, const int* in_sizes, int n_in,
                              void* d_out, int out_size)
{
    const float* x      = (const float*)d_in[0];
    const float* w_attn = (const float*)d_in[1];
    const float* b_attn = (const float*)d_in[2];
    const float* w_proj = (const float*)d_in[3];
    const float* b_proj = (const float*)d_in[4];
    float* out = (float*)d_out;

    cudaFuncSetAttribute(tc_gemm,
                         cudaFuncAttributeMaxDynamicSharedMemorySize, GEMM_SMEM);
    cudaFuncSetAttribute(attn_mma_kernel,
                         cudaFuncAttributeMaxDynamicSharedMemorySize, ATTN_SMEM);

    // 0) Pre-round operands to tf32 in gmem (dst selected inside kernel)
    cvt_tf32_kernel<<<(MTOK * NXC) / 1024, 256>>>(x, 0);
    cvt_tf32_kernel<<<(NXC * 3 * NXC) / 1024, 256>>>(w_attn, 1);
    cvt_tf32_kernel<<<(NXC * NXC) / 1024, 256>>>(w_proj, 2);

    // 1) QKV GEMM (cp.async, cvt-free mainloop); K written transposed
    tc_gemm<<<dim3(24, 32), 256, GEMM_SMEM>>>(b_attn, nullptr, NXC, 3 * NXC, 1);

    // 2) Tensor-core causal flash attention (heavy-first, raw staging)
    attn_mma_kernel<<<dim3(BB * HH, SS / 128), 256, ATTN_SMEM>>>();

    // 3) Projection (cp.async, cvt-free mainloop)
    tc_gemm<<<dim3(8, 32), 256, GEMM_SMEM>>>(b_proj, out, NXC, NXC, 0);
}